// round 2
// baseline (speedup 1.0000x reference)
#include <cuda_runtime.h>

#define THREADS 256
#define S_CTA   64
#define PAD     68

#define OFF_HT    0                  // 128 x PAD : hT (alias: ctxT)
#define OFF_ARCH  8704               //  64 x PAD : archT (live until stage E)
#define OFF_QKV   13056              // 192 x PAD : qkvT (alias: xT 128xPAD)
#define OFF_COLS  26112              // int[5*64]
#define OFF_HW    26432              // int[64]
#define OFF_HWEMB 26496              // float[256]
#define SMEM_FLOATS 26752
#define SMEM_BYTES  (SMEM_FLOATS * 4)

__device__ float g_W1T[75 * 128];
__device__ float g_W2T[128 * 64];
__device__ float g_inT[64 * 192];
__device__ float g_WoT[64 * 64];
__device__ float g_W3T[64 * 32];
__device__ float g_qkv0[4 * 192];
__device__ float g_s00[16];

#define OUTER4(acc, h, w) do { \
    acc[0][0] += (h).x*(w).x; acc[0][1] += (h).x*(w).y; acc[0][2] += (h).x*(w).z; acc[0][3] += (h).x*(w).w; \
    acc[1][0] += (h).y*(w).x; acc[1][1] += (h).y*(w).y; acc[1][2] += (h).y*(w).z; acc[1][3] += (h).y*(w).w; \
    acc[2][0] += (h).z*(w).x; acc[2][1] += (h).z*(w).y; acc[2][2] += (h).z*(w).z; acc[2][3] += (h).z*(w).w; \
    acc[3][0] += (h).w*(w).x; acc[3][1] += (h).w*(w).y; acc[3][2] += (h).w*(w).z; acc[3][3] += (h).w*(w).w; \
} while (0)

__global__ void prep_transpose(const float* __restrict__ W1, const float* __restrict__ W2,
                               const float* __restrict__ ipw, const float* __restrict__ opw,
                               const float* __restrict__ W3)
{
    int t = blockIdx.x * blockDim.x + threadIdx.x;
    int NT = gridDim.x * blockDim.x;
    for (int i = t; i < 75 * 128; i += NT) g_W1T[i] = W1[(i & 127) * 75 + (i >> 7)];
    for (int i = t; i < 128 * 64; i += NT) g_W2T[i] = W2[(i & 63) * 128 + (i >> 6)];
    for (int i = t; i < 64 * 192; i += NT) g_inT[i] = ipw[(i % 192) * 64 + (i / 192)];
    for (int i = t; i < 64 * 64;  i += NT) g_WoT[i] = opw[(i & 63) * 64 + (i >> 6)];
    for (int i = t; i < 64 * 32;  i += NT) g_W3T[i] = W3[(i & 31) * 64 + (i >> 5)];
}

__global__ void prep_qkv0(const float* __restrict__ ipw, const float* __restrict__ ipb,
                          const float* __restrict__ hw_embed)
{
    int t = threadIdx.x;
    if (t < 768) {
        int hw = t / 192, o = t % 192;
        float acc = ipb[o];
        #pragma unroll 8
        for (int d = 0; d < 64; d++) acc += ipw[o * 64 + d] * hw_embed[hw * 64 + d];
        g_qkv0[t] = acc;
    }
    __syncthreads();
    if (t < 16) {
        int hw = t >> 2, hh = t & 3;
        const float* q0 = g_qkv0 + hw * 192 + hh * 16;
        const float* k0 = q0 + 64;
        float acc = 0.f;
        #pragma unroll
        for (int j = 0; j < 16; j++) acc += q0[j] * k0[j];
        g_s00[t] = acc * 0.25f;
    }
}

__global__ void __launch_bounds__(THREADS, 2)
mhlp_main(const int* __restrict__ hw_idx, const int* __restrict__ op_idx,
          const int* __restrict__ wd_idx, const float* __restrict__ hw_embed,
          const float* __restrict__ b1,   const float* __restrict__ b2,
          const float* __restrict__ ln1g, const float* __restrict__ ln1b,
          const float* __restrict__ ipb,  const float* __restrict__ opb,
          const float* __restrict__ ln2g, const float* __restrict__ ln2b,
          const float* __restrict__ b3,   const float* __restrict__ W4,
          const float* __restrict__ b4,   float* __restrict__ out)
{
    extern __shared__ float sm[];
    float* s_hT   = sm + OFF_HT;
    float* s_arch = sm + OFF_ARCH;
    float* s_qkv  = sm + OFF_QKV;
    int*   s_col  = (int*)(sm + OFF_COLS);
    int*   s_hw   = (int*)(sm + OFF_HW);
    float* s_hwe  = sm + OFF_HWEMB;
    float* s_ctx  = sm + OFF_HT;     // alias, after hT dead
    float* s_x    = sm + OFF_QKV;    // alias, after qkv dead

    const int t    = threadIdx.x;
    const int base = blockIdx.x * S_CTA;

    // stage 0: indices + hw embedding into smem
    s_hwe[t] = hw_embed[t];
    if (t < S_CTA) {
        s_hw[t] = hw_idx[base + t];
        #pragma unroll
        for (int l = 0; l < 5; l++) {
            int op = op_idx[(base + t) * 5 + l];
            int wd = wd_idx[(base + t) * 5 + l];
            s_col[l * S_CTA + t] = l * 15 + op * 3 + wd;
        }
    }
    __syncthreads();

    // stage A: h = relu(b1 + sum_l W1col)  -> s_hT[k][s]
    {
        const int s = t & 63, grp = t >> 6;     // conflict-free: s is fast axis
        int c[5];
        #pragma unroll
        for (int l = 0; l < 5; l++) c[l] = s_col[l * S_CTA + s];
        #pragma unroll
        for (int i = 0; i < 8; i++) {
            int k4 = grp * 32 + i * 4;
            float4 a = __ldg((const float4*)(b1 + k4));
            #pragma unroll
            for (int l = 0; l < 5; l++) {
                float4 w = __ldg((const float4*)(g_W1T + c[l] * 128 + k4));
                a.x += w.x; a.y += w.y; a.z += w.z; a.w += w.w;
            }
            s_hT[(k4 + 0) * PAD + s] = fmaxf(a.x, 0.f);
            s_hT[(k4 + 1) * PAD + s] = fmaxf(a.y, 0.f);
            s_hT[(k4 + 2) * PAD + s] = fmaxf(a.z, 0.f);
            s_hT[(k4 + 3) * PAD + s] = fmaxf(a.w, 0.f);
        }
    }
    __syncthreads();

    const int sg = t & 15, og = t >> 4;
    const int s0 = sg * 4, o0 = og * 4;

    // stage B: arch_pre = h @ W2^T + b2 -> s_arch[o][s]
    {
        float acc[4][4] = {};
        #pragma unroll 4
        for (int k = 0; k < 128; k++) {
            float4 h = *(const float4*)(s_hT + k * PAD + s0);
            float4 w = __ldg((const float4*)(g_W2T + k * 64 + o0));
            OUTER4(acc, h, w);
        }
        #pragma unroll
        for (int j = 0; j < 4; j++) {
            float bb = __ldg(b2 + o0 + j);
            #pragma unroll
            for (int i = 0; i < 4; i++)
                s_arch[(o0 + j) * PAD + s0 + i] = acc[i][j] + bb;
        }
    }
    __syncthreads();

    // stage B2: LayerNorm1 (1 thread / sample)
    if (t < S_CTA) {
        float sum = 0.f, sq = 0.f;
        #pragma unroll 8
        for (int d = 0; d < 64; d++) { float v = s_arch[d * PAD + t]; sum += v; sq += v * v; }
        float m   = sum * (1.f / 64.f);
        float var = fmaxf(sq * (1.f / 64.f) - m * m, 0.f);
        float inv = rsqrtf(var + 1e-5f);
        #pragma unroll 8
        for (int d = 0; d < 64; d++) {
            float v = (s_arch[d * PAD + t] - m) * inv;
            s_arch[d * PAD + t] = v * __ldg(ln1g + d) + __ldg(ln1b + d);
        }
    }
    __syncthreads();

    // stage C: qkv1 = arch @ in_proj^T + b -> s_qkv[o][s]
    #pragma unroll 1
    for (int ob = 0; ob < 3; ob++) {
        const int oo = ob * 64 + o0;
        float acc[4][4] = {};
        #pragma unroll 4
        for (int d = 0; d < 64; d++) {
            float4 h = *(const float4*)(s_arch + d * PAD + s0);
            float4 w = __ldg((const float4*)(g_inT + d * 192 + oo));
            OUTER4(acc, h, w);
        }
        #pragma unroll
        for (int j = 0; j < 4; j++) {
            float bb = __ldg(ipb + oo + j);
            #pragma unroll
            for (int i = 0; i < 4; i++)
                s_qkv[(oo + j) * PAD + s0 + i] = acc[i][j] + bb;
        }
    }
    __syncthreads();

    // stage D: attention (1 thread per (sample, head)) -> s_ctx[tok*64+d][s]
    {
        const int s = t & 63, hh = t >> 6;      // s fast axis: conflict-free
        const int rq = hh * 16;
        float q1[16], k1[16], v1[16];
        #pragma unroll
        for (int j = 0; j < 16; j++) {
            q1[j] = s_qkv[(rq + j) * PAD + s];
            k1[j] = s_qkv[(64 + rq + j) * PAD + s];
            v1[j] = s_qkv[(128 + rq + j) * PAD + s];
        }
        const int hw = s_hw[s];
        const float* q0 = g_qkv0 + hw * 192 + rq;
        const float* k0 = q0 + 64;
        const float* v0 = q0 + 128;
        float s01 = 0.f, s10 = 0.f, s11 = 0.f;
        #pragma unroll
        for (int j = 0; j < 16; j++) {
            float q0j = __ldg(q0 + j), k0j = __ldg(k0 + j);
            s01 += q0j * k1[j];
            s10 += q1[j] * k0j;
            s11 += q1[j] * k1[j];
        }
        s01 *= 0.25f; s10 *= 0.25f; s11 *= 0.25f;
        float s00 = __ldg(g_s00 + hw * 4 + hh);
        float m0 = fmaxf(s00, s01);
        float e00 = __expf(s00 - m0), e01 = __expf(s01 - m0);
        float r0 = __frcp_rn(e00 + e01);
        float a00 = e00 * r0, a01 = e01 * r0;
        float m1 = fmaxf(s10, s11);
        float e10 = __expf(s10 - m1), e11 = __expf(s11 - m1);
        float r1 = __frcp_rn(e10 + e11);
        float a10 = e10 * r1, a11 = e11 * r1;
        #pragma unroll
        for (int j = 0; j < 16; j++) {
            float v0j = __ldg(v0 + j);
            s_ctx[(rq + j) * PAD + s]      = a00 * v0j + a01 * v1[j];
            s_ctx[(64 + rq + j) * PAD + s] = a10 * v0j + a11 * v1[j];
        }
    }
    __syncthreads();

    // stage E: attn_out = ctx @ out_proj^T + b + residual -> s_x[tok*64+o][s]
    #pragma unroll 1
    for (int tok = 0; tok < 2; tok++) {
        float acc[4][4] = {};
        #pragma unroll 4
        for (int d = 0; d < 64; d++) {
            float4 c = *(const float4*)(s_ctx + (tok * 64 + d) * PAD + s0);
            float4 w = __ldg((const float4*)(g_WoT + d * 64 + o0));
            OUTER4(acc, c, w);
        }
        #pragma unroll
        for (int j = 0; j < 4; j++) {
            float bb = __ldg(opb + o0 + j);
            #pragma unroll
            for (int i = 0; i < 4; i++) {
                float res = tok ? s_arch[(o0 + j) * PAD + s0 + i]
                                : s_hwe[s_hw[s0 + i] * 64 + (o0 + j)];
                s_x[(tok * 64 + o0 + j) * PAD + s0 + i] = acc[i][j] + bb + res;
            }
        }
    }
    __syncthreads();

    // stage E2: LayerNorm2 (1 thread per (token, sample))
    if (t < 128) {
        const int s = t & 63, tok = t >> 6;
        float* xp = s_x + tok * 64 * PAD + s;
        float sum = 0.f, sq = 0.f;
        #pragma unroll 8
        for (int d = 0; d < 64; d++) { float v = xp[d * PAD]; sum += v; sq += v * v; }
        float m   = sum * (1.f / 64.f);
        float var = fmaxf(sq * (1.f / 64.f) - m * m, 0.f);
        float inv = rsqrtf(var + 1e-5f);
        #pragma unroll 8
        for (int d = 0; d < 64; d++) {
            float v = (xp[d * PAD] - m) * inv;
            xp[d * PAD] = v * __ldg(ln2g + d) + __ldg(ln2b + d);
        }
    }
    __syncthreads();

    // stage F: pooled -> relu(@W3^T+b3) @ W4^T + b4 -> out
    {
        const int s = t >> 2, hh = t & 3;   // 4-lane groups share sample (smem broadcast)
        float acc[8];
        #pragma unroll
        for (int o = 0; o < 8; o++) acc[o] = __ldg(b3 + hh * 8 + o);
        #pragma unroll 4
        for (int d = 0; d < 64; d++) {
            float p = 0.5f * (s_x[d * PAD + s] + s_x[(64 + d) * PAD + s]);
            float4 w0 = __ldg((const float4*)(g_W3T + d * 32 + hh * 8));
            float4 w1 = __ldg((const float4*)(g_W3T + d * 32 + hh * 8 + 4));
            acc[0] += p * w0.x; acc[1] += p * w0.y; acc[2] += p * w0.z; acc[3] += p * w0.w;
            acc[4] += p * w1.x; acc[5] += p * w1.y; acc[6] += p * w1.z; acc[7] += p * w1.w;
        }
        float part = 0.f;
        #pragma unroll
        for (int o = 0; o < 8; o++)
            part += fmaxf(acc[o], 0.f) * __ldg(W4 + hh * 8 + o);
        part += __shfl_down_sync(0xffffffffu, part, 2);
        part += __shfl_down_sync(0xffffffffu, part, 1);
        if (hh == 0) out[base + s] = part + __ldg(b4);
    }
}

extern "C" void kernel_launch(void* const* d_in, const int* in_sizes, int n_in,
                              void* d_out, int out_size)
{
    const int*   hw_idx   = (const int*)  d_in[0];
    const int*   op_idx   = (const int*)  d_in[1];
    const int*   wd_idx   = (const int*)  d_in[2];
    const float* hw_embed = (const float*)d_in[3];
    const float* W1       = (const float*)d_in[4];
    const float* b1       = (const float*)d_in[5];
    const float* W2       = (const float*)d_in[6];
    const float* b2       = (const float*)d_in[7];
    const float* ln1g     = (const float*)d_in[8];
    const float* ln1b     = (const float*)d_in[9];
    const float* ipw      = (const float*)d_in[10];
    const float* ipb      = (const float*)d_in[11];
    const float* opw      = (const float*)d_in[12];
    const float* opb      = (const float*)d_in[13];
    const float* ln2g     = (const float*)d_in[14];
    const float* ln2b     = (const float*)d_in[15];
    const float* W3       = (const float*)d_in[16];
    const float* b3       = (const float*)d_in[17];
    const float* W4       = (const float*)d_in[18];
    const float* b4       = (const float*)d_in[19];
    float* out = (float*)d_out;

    static bool attr_set = false;
    if (!attr_set) {
        cudaFuncSetAttribute(mhlp_main, cudaFuncAttributeMaxDynamicSharedMemorySize, SMEM_BYTES);
        attr_set = true;
    }

    prep_transpose<<<40, 256>>>(W1, W2, ipw, opw, W3);
    prep_qkv0<<<1, 768>>>(ipw, ipb, hw_embed);

    const int B = in_sizes[0];
    mhlp_main<<<B / S_CTA, THREADS, SMEM_BYTES>>>(
        hw_idx, op_idx, wd_idx, hw_embed, b1, b2, ln1g, ln1b,
        ipb, opb, ln2g, ln2b, b3, W4, b4, out);
}